// round 16
// baseline (speedup 1.0000x reference)
#include <cuda_runtime.h>
#include <math.h>
#include <stdint.h>

#define NROWS 131072
#define DIM 64
#define KC 64
#define ITERS 10
#define TPB 256
#define MT 128                    // rows per tile
#define NT (NROWS / MT)           // 1024 tiles
#define MAXGRID 148
#define NSLOTS (2 * MAXGRID)      // max partial slots (1 per block)
#define SLOTW 68                  // floats per (kc, slot) chunk; d==64 -> colsum

// ---------------- device globals (no cudaMalloc allowed) ----------------
__device__ float g_clusters[KC * DIM];
__device__ float g_prev[KC * DIM];          // clusters used by last active iteration
__device__ float g_part[(size_t)KC * NSLOTS * SLOTW];    // kc-major: [kc][slot][d]
__device__ float g_normk[KC];
__device__ float g_wsq[NROWS];
__device__ int   g_done;
__device__ volatile int g_sync[2];

// ---------------- helpers ----------------
__device__ __forceinline__ uint32_t f2t(float x) {
    uint32_t u;
    asm("cvt.rna.tf32.f32 %0, %1;" : "=r"(u) : "f"(x));
    return u;
}
__device__ __forceinline__ float fsqrt_fast(float x) {
    float r;
    asm("sqrt.approx.f32 %0, %1;" : "=f"(r) : "f"(x));
    return r;
}
__device__ __forceinline__ void mma8(float c[4], uint32_t a0, uint32_t a1, uint32_t a2,
                                     uint32_t a3, uint32_t b0, uint32_t b1) {
    asm("mma.sync.aligned.m16n8k8.row.col.f32.tf32.tf32.f32 "
        "{%0,%1,%2,%3},{%4,%5,%6,%7},{%8,%9},{%0,%1,%2,%3};"
        : "+f"(c[0]), "+f"(c[1]), "+f"(c[2]), "+f"(c[3])
        : "r"(a0), "r"(a1), "r"(a2), "r"(a3), "r"(b0), "r"(b1));
}
__device__ __forceinline__ void cp_async16(uint32_t smem_addr, const void* gptr) {
    asm volatile("cp.async.cg.shared.global [%0], [%1], 16;"
                 :: "r"(smem_addr), "l"(gptr));
}
#define CP_COMMIT() asm volatile("cp.async.commit_group;" ::: "memory")
#define CP_WAIT0()  asm volatile("cp.async.wait_group 0;" ::: "memory")
#define BITS(x) (__float_as_uint(x))
// permuted k layout: pos(k) = (k&3)*20 + (k>>2), row stride 80 -> float4 = 2 mma k-steps
#define CLP_POS(k) (((k) & 3) * 20 + ((k) >> 2))

// deterministic grid-wide sync: monotonic counters, per-launch target
__device__ __forceinline__ void gsync(int j, int target) {
    __syncthreads();
    if (threadIdx.x == 0) {
        __threadfence();
        atomicAdd((int*)&g_sync[j], 1);
        while (g_sync[j] < target) { }
        __threadfence();
    }
    __syncthreads();
}

// ---------------- init: flags, counters, cluster copy, ||w||^2 ----------------
__global__ void init_kernel(const float* __restrict__ W, const float* __restrict__ C0) {
    int gid = blockIdx.x * blockDim.x + threadIdx.x;   // NROWS threads
    if (gid == 0) { g_done = 0; g_sync[0] = 0; g_sync[1] = 0; }
    if (gid < KC * DIM) g_clusters[gid] = C0[gid];
    const float4* p = (const float4*)(W + (size_t)gid * DIM);
    float s = 0.f;
#pragma unroll
    for (int j = 0; j < 16; j++) {
        float4 v = p[j];
        s += v.x * v.x + v.y * v.y + v.z * v.z + v.w * v.w;
    }
    g_wsq[gid] = s;
}

// ---------------- fully fused iteration kernel (296 blocks, occ 2) ----------------
// W tile arrives via cp.async; an in-smem pass rounds it to tf32 (rna) before use.
__global__ __launch_bounds__(TPB, 2) void iter_fused(int it, const float* __restrict__ W) {
    if (g_done) return;
    extern __shared__ float sm[];
    float* clp  = sm;          // [64][80] clusters, k-permuted tf32(rna)
    float* csq  = sm + 5120;   // [64] exact ||c||^2
    float* w    = sm + 5184;   // [128][72] W tile tf32(rna); col64=1, cols65-71=0
    float* att  = sm + 14400;  // [128][72] attn tile tf32(rna); c2 stage at end
    float* wsqs = sm + 23616;  // [128]

    const int tid = threadIdx.x;
    const int lane = tid & 31, wid = tid >> 5;
    const int gid = lane >> 2, tig = lane & 3;
    const int m1 = wid * 16;            // GEMM1 row offset
    const int m2 = (wid & 3) * 16;      // GEMM2 kc offset
    const int rh = (wid >> 2) * 64;     // GEMM2 row-half offset
    const int target = (it + 1) * (int)gridDim.x;

    // this thread's 8 tile chunks (generic ptr + smem u32 for cp.async)
    float* w_ptr[8];
    uint32_t w_dst[8];
#pragma unroll
    for (int j = 0; j < 8; j++) {
        const int i = tid * 4 + j * 1024;
        w_ptr[j] = w + (i >> 6) * 72 + (i & 63);
        w_dst[j] = (uint32_t)__cvta_generic_to_shared(w_ptr[j]);
    }

    for (int i = tid; i < KC * DIM; i += TPB) {
        int n = i >> 6, k = i & 63;
        clp[n * 80 + CLP_POS(k)] = __uint_as_float(f2t(g_clusters[i]));
    }
    if (tid < KC) {
        float s = 0.f;
#pragma unroll
        for (int d = 0; d < DIM; d++) { float v = g_clusters[tid * DIM + d]; s += v * v; }
        csq[tid] = s;
    }
    // persistent ones/zeros in cols 64..71 of w (colsum trick)
    for (int i = tid; i < MT * 8; i += TPB) {
        int r = i >> 3, c = i & 7;
        w[r * 72 + 64 + c] = (c == 0) ? 1.0f : 0.0f;
    }

    float c2[9][4];
#pragma unroll
    for (int j = 0; j < 9; j++) { c2[j][0] = c2[j][1] = c2[j][2] = c2[j][3] = 0.f; }

    // wsq register prefetch (1 reg; cross-tile)
    float wsq_pf = (tid < MT) ? g_wsq[(size_t)blockIdx.x * MT + tid] : 0.f;

    for (int tile = blockIdx.x; tile < NT; tile += gridDim.x) {
        __syncthreads();   // w/att free (previous GEMM2 done; init done on first pass)
        // async copy of this tile's W rows straight into smem
        {
            const float* src = W + (size_t)tile * MT * DIM + tid * 4;
#pragma unroll
            for (int j = 0; j < 8; j++) cp_async16(w_dst[j], src + j * 1024);
            CP_COMMIT();
        }
        if (tid < MT) wsqs[tid] = wsq_pf;
        CP_WAIT0();
        // transient in-smem tf32(rna) rounding of this thread's own chunks
#pragma unroll
        for (int j = 0; j < 8; j++) {
            float4 v = *(float4*)w_ptr[j];
            v.x = __uint_as_float(f2t(v.x));
            v.y = __uint_as_float(f2t(v.y));
            v.z = __uint_as_float(f2t(v.z));
            v.w = __uint_as_float(f2t(v.w));
            *(float4*)w_ptr[j] = v;
        }
        __syncthreads();

        // prefetch next tile's wsq (retires under GEMM1+softmax)
        const int nt = tile + (int)gridDim.x;
        if (nt < NT && tid < MT) wsq_pf = g_wsq[(size_t)nt * MT + tid];

        // ---- GEMM1: C1[row][kc] = W * C^T  (B via vectorized permuted loads) ----
        float c1[8][4];
#pragma unroll
        for (int j = 0; j < 8; j++) { c1[j][0] = c1[j][1] = c1[j][2] = c1[j][3] = 0.f; }
        const float* Ab = w + (m1 + gid) * 72 + tig;
        const float* Bp = clp + gid * 80 + tig * 20;
#pragma unroll
        for (int t = 0; t < 4; t++) {
            const int k0 = 16 * t;
            uint32_t a00 = BITS(Ab[k0]),     a01 = BITS(Ab[576 + k0]);
            uint32_t a02 = BITS(Ab[k0 + 4]), a03 = BITS(Ab[576 + k0 + 4]);
            uint32_t a10 = BITS(Ab[k0 + 8]),  a11 = BITS(Ab[576 + k0 + 8]);
            uint32_t a12 = BITS(Ab[k0 + 12]), a13 = BITS(Ab[576 + k0 + 12]);
#pragma unroll
            for (int j = 0; j < 8; j++) {
                float4 b = *(const float4*)(Bp + j * 640 + 4 * t);
                mma8(c1[j], a00, a01, a02, a03, BITS(b.x), BITS(b.y));
                mma8(c1[j], a10, a11, a12, a13, BITS(b.z), BITS(b.w));
            }
        }

        // ---- softmax (no max-subtraction: dists in [0,~25], exp(-d) exact ratio) ----
        {
            float ws = wsqs[m1 + gid];
            float e[16], s = 0.f;
#pragma unroll
            for (int j = 0; j < 8; j++) {
                float c0 = csq[8 * j + 2 * tig], c1v = csq[8 * j + 2 * tig + 1];
                float e0 = __expf(-fsqrt_fast(fmaxf(ws + c0 - 2.f * c1[j][0], 0.f)));
                float e1 = __expf(-fsqrt_fast(fmaxf(ws + c1v - 2.f * c1[j][1], 0.f)));
                e[2 * j] = e0; e[2 * j + 1] = e1;
                s += e0 + e1;
            }
            s += __shfl_xor_sync(0xffffffffu, s, 1);
            s += __shfl_xor_sync(0xffffffffu, s, 2);
            float inv = 1.f / s;
            float* wA = att + (m1 + gid) * 72 + 2 * tig;
#pragma unroll
            for (int j = 0; j < 8; j++) {
                float2 v = make_float2(__uint_as_float(f2t(e[2 * j] * inv)),
                                       __uint_as_float(f2t(e[2 * j + 1] * inv)));
                *(float2*)(wA + 8 * j) = v;
            }
        }
        {
            float ws = wsqs[m1 + gid + 8];
            float e[16], s = 0.f;
#pragma unroll
            for (int j = 0; j < 8; j++) {
                float c0 = csq[8 * j + 2 * tig], c1v = csq[8 * j + 2 * tig + 1];
                float e0 = __expf(-fsqrt_fast(fmaxf(ws + c0 - 2.f * c1[j][2], 0.f)));
                float e1 = __expf(-fsqrt_fast(fmaxf(ws + c1v - 2.f * c1[j][3], 0.f)));
                e[2 * j] = e0; e[2 * j + 1] = e1;
                s += e0 + e1;
            }
            s += __shfl_xor_sync(0xffffffffu, s, 1);
            s += __shfl_xor_sync(0xffffffffu, s, 2);
            float inv = 1.f / s;
            float* wB = att + (m1 + gid + 8) * 72 + 2 * tig;
#pragma unroll
            for (int j = 0; j < 8; j++) {
                float2 v = make_float2(__uint_as_float(f2t(e[2 * j] * inv)),
                                       __uint_as_float(f2t(e[2 * j + 1] * inv)));
                *(float2*)(wB + 8 * j) = v;
            }
        }
        __syncthreads();

        // ---- GEMM2: C2[kc][d] += attn^T * W  (9th n-frag vs ones col = colsum) ----
        const float* A2 = att + (rh + tig) * 72 + m2 + gid;
        const float* B2 = w + (rh + tig) * 72 + gid;
#pragma unroll 4
        for (int s = 0; s < 8; s++) {
            const int o = s * 8 * 72;
            uint32_t a0 = BITS(A2[o]);
            uint32_t a1 = BITS(A2[o + 8]);
            uint32_t a2 = BITS(A2[o + 4 * 72]);
            uint32_t a3 = BITS(A2[o + 4 * 72 + 8]);
#pragma unroll
            for (int j = 0; j < 9; j++) {
                uint32_t b0 = BITS(B2[o + 8 * j]);
                uint32_t b1 = BITS(B2[o + 4 * 72 + 8 * j]);
                mma8(c2[j], a0, a1, a2, a3, b0, b1);
            }
        }
    }

    // ---- combine row-halves in smem, write ONE partial slot per block (kc-major gmem) ----
    __syncthreads();
    {
        float* stage = att;             // [64][72] c2 of row-half 1
        if (rh) {
#pragma unroll
            for (int j = 0; j < 8; j++) {
                *(float2*)(stage + (m2 + gid) * 72 + 8 * j + 2 * tig) = make_float2(c2[j][0], c2[j][1]);
                *(float2*)(stage + (m2 + gid + 8) * 72 + 8 * j + 2 * tig) = make_float2(c2[j][2], c2[j][3]);
            }
            if (tig == 0) {
                stage[(m2 + gid) * 72 + 64] = c2[8][0];
                stage[(m2 + gid + 8) * 72 + 64] = c2[8][2];
            }
        }
        __syncthreads();
        if (!rh) {
            // row kc lives at g_part[kc*NSLOTS*SLOTW + blockIdx.x*SLOTW + d]
            float* P0 = g_part + (size_t)blockIdx.x * SLOTW;
#pragma unroll
            for (int j = 0; j < 8; j++) {
                float2 s0 = *(float2*)(stage + (m2 + gid) * 72 + 8 * j + 2 * tig);
                float2 s1 = *(float2*)(stage + (m2 + gid + 8) * 72 + 8 * j + 2 * tig);
                *(float2*)(P0 + (size_t)(m2 + gid) * NSLOTS * SLOTW + 8 * j + 2 * tig) =
                    make_float2(c2[j][0] + s0.x, c2[j][1] + s0.y);
                *(float2*)(P0 + (size_t)(m2 + gid + 8) * NSLOTS * SLOTW + 8 * j + 2 * tig) =
                    make_float2(c2[j][2] + s1.x, c2[j][3] + s1.y);
            }
            if (tig == 0) {
                P0[(size_t)(m2 + gid) * NSLOTS * SLOTW + 64] = c2[8][0] + stage[(m2 + gid) * 72 + 64];
                P0[(size_t)(m2 + gid + 8) * NSLOTS * SLOTW + 64] = c2[8][2] + stage[(m2 + gid + 8) * 72 + 64];
            }
        }
    }

    gsync(0, target);

    // ---- blocks 0..63 reduce partials for their k (coalesced contiguous scan) ----
    float nv = 0.f, ov = 0.f;
    const int kblk = blockIdx.x;
    if (kblk < 64) {
        float* r_num = sm;          // [4][64]
        float* r_den = sm + 256;    // [4]
        float* s_nrm = sm + 264;    // [2]
        const int q = tid >> 6, d = tid & 63;
        const int nslots = (int)gridDim.x;
        float s = 0.f, sden = 0.f;
        const float* base = g_part + (size_t)kblk * NSLOTS * SLOTW;
#pragma unroll 4
        for (int b = q; b < nslots; b += 4) {
            const float* P = base + (size_t)b * SLOTW;
            s += P[d];
            if (d == 0) sden += P[64];
        }
        r_num[q * 64 + d] = s;
        if (d == 0) r_den[q] = sden;
        __syncthreads();
        if (tid < 64) {
            float num = (r_num[tid] + r_num[64 + tid]) + (r_num[128 + tid] + r_num[192 + tid]);
            float den = (r_den[0] + r_den[1]) + (r_den[2] + r_den[3]);
            nv = num / den;
            ov = g_clusters[kblk * 64 + tid];
            float x = (nv - ov) * (nv - ov);
#pragma unroll
            for (int o = 16; o > 0; o >>= 1) x += __shfl_xor_sync(0xffffffffu, x, o);
            if ((tid & 31) == 0) s_nrm[tid >> 5] = x;
        }
        __syncthreads();
        if (tid == 0) g_normk[kblk] = s_nrm[0] + s_nrm[1];
    }

    gsync(1, target);

    // ---- convergence decision (redundant per block) + commit ----
    if (kblk < 64) {
        __shared__ int s_conv;
        if (tid == 0) {
            float t = 0.f;
            for (int k = 0; k < 64; k++) t += g_normk[k];
            int conv = (sqrtf(t) <= 1e-4f) ? 1 : 0;
            s_conv = conv;
            if (kblk == 0 && conv) g_done = 1;   // freeze for remaining launches
        }
        __syncthreads();
        if (tid < 64) {
            g_prev[kblk * 64 + tid] = ov;
            g_clusters[kblk * 64 + tid] = s_conv ? ov : nv;
        }
    }
}

// ---------------- fused final: attn (tf32 GEMM1 + fp32 softmax) + compressed (tf32 GEMM3) ----------------
__global__ __launch_bounds__(TPB, 2) void final_fused(const float* __restrict__ W,
                                                      float* __restrict__ attn_out,
                                                      float* __restrict__ comp,
                                                      float* __restrict__ clus_out) {
    extern __shared__ float sm[];
    float* clp = sm;          // [64][80] tf32(g_prev), k-permuted (B of GEMM1)
    float* csq = sm + 5120;   // [64] exact ||c_prev||^2
    float* w   = sm + 5184;   // [128][72] tf32 W tile
    float* att = sm + 14400;  // [128][72] fp32 attn
    float* csp = sm + 23616;  // [64][80] tf32(g_clusters), d-major k-permuted (B of GEMM3)
    float* wsq = sm + 28736;  // [128]

    const int tid = threadIdx.x;
    const int lane = tid & 31, wid = tid >> 5;
    const int gid = lane >> 2, tig = lane & 3;
    const int m1 = wid * 16;
    const size_t row0 = (size_t)blockIdx.x * MT;

    for (int i = tid; i < KC * DIM; i += TPB) {
        int kc = i >> 6, d = i & 63;
        clp[kc * 80 + CLP_POS(d)] = __uint_as_float(f2t(g_prev[i]));      // B1[n=kc][k=d]
        float cv = g_clusters[i];
        csp[d * 80 + CLP_POS(kc)] = __uint_as_float(f2t(cv));             // B3[n=d][k=kc]
        if (blockIdx.x == 0) clus_out[i] = cv;
    }
    if (tid < KC) {
        float s = 0.f;
#pragma unroll
        for (int d = 0; d < DIM; d++) { float v = g_prev[tid * DIM + d]; s += v * v; }
        csq[tid] = s;
    }
    for (int i = tid * 4; i < MT * DIM; i += TPB * 4) {
        float4 v = *(const float4*)(W + row0 * DIM + i);
        v.x = __uint_as_float(f2t(v.x));
        v.y = __uint_as_float(f2t(v.y));
        v.z = __uint_as_float(f2t(v.z));
        v.w = __uint_as_float(f2t(v.w));
        *(float4*)(w + (i >> 6) * 72 + (i & 63)) = v;
    }
    if (tid < MT) wsq[tid] = g_wsq[row0 + tid];
    __syncthreads();

    // ---- GEMM1 (tf32 mma, vectorized B): C1[row][kc] = W * C_prev^T ----
    float c1[8][4];
#pragma unroll
    for (int j = 0; j < 8; j++) { c1[j][0] = c1[j][1] = c1[j][2] = c1[j][3] = 0.f; }
    {
        const float* Ab = w + (m1 + gid) * 72 + tig;
        const float* Bp = clp + gid * 80 + tig * 20;
#pragma unroll
        for (int t = 0; t < 4; t++) {
            const int k0 = 16 * t;
            uint32_t a00 = BITS(Ab[k0]),     a01 = BITS(Ab[576 + k0]);
            uint32_t a02 = BITS(Ab[k0 + 4]), a03 = BITS(Ab[576 + k0 + 4]);
            uint32_t a10 = BITS(Ab[k0 + 8]),  a11 = BITS(Ab[576 + k0 + 8]);
            uint32_t a12 = BITS(Ab[k0 + 12]), a13 = BITS(Ab[576 + k0 + 12]);
#pragma unroll
            for (int j = 0; j < 8; j++) {
                float4 b = *(const float4*)(Bp + j * 640 + 4 * t);
                mma8(c1[j], a00, a01, a02, a03, BITS(b.x), BITS(b.y));
                mma8(c1[j], a10, a11, a12, a13, BITS(b.z), BITS(b.w));
            }
        }
    }

    // ---- softmax rows (no max-subtraction; fp32 attn into smem) ----
    {
        float ws = wsq[m1 + gid];
        float e[16], s = 0.f;
#pragma unroll
        for (int j = 0; j < 8; j++) {
            float c0 = csq[8 * j + 2 * tig], c1v = csq[8 * j + 2 * tig + 1];
            float e0 = __expf(-fsqrt_fast(fmaxf(ws + c0 - 2.f * c1[j][0], 0.f)));
            float e1 = __expf(-fsqrt_fast(fmaxf(ws + c1v - 2.f * c1[j][1], 0.f)));
            e[2 * j] = e0; e[2 * j + 1] = e1;
            s += e0 + e1;
        }
        s += __shfl_xor_sync(0xffffffffu, s, 1);
        s += __shfl_xor_sync(0xffffffffu, s, 2);
        float inv = 1.f / s;
        float* wA = att + (m1 + gid) * 72 + 2 * tig;
#pragma unroll
        for (int j = 0; j < 8; j++)
            *(float2*)(wA + 8 * j) = make_float2(e[2 * j] * inv, e[2 * j + 1] * inv);
    }
    {
        float ws = wsq[m1 + gid + 8];
        float e[16], s = 0.f;
#pragma unroll
        for (int j = 0; j < 8; j++) {
            float c0 = csq[8 * j + 2 * tig], c1v = csq[8 * j + 2 * tig + 1];
            float e0 = __expf(-fsqrt_fast(fmaxf(ws + c0 - 2.f * c1[j][2], 0.f)));
            float e1 = __expf(-fsqrt_fast(fmaxf(ws + c1v - 2.f * c1[j][3], 0.f)));
            e[2 * j] = e0; e[2 * j + 1] = e1;
            s += e0 + e1;
        }
        s += __shfl_xor_sync(0xffffffffu, s, 1);
        s += __shfl_xor_sync(0xffffffffu, s, 2);
        float inv = 1.f / s;
        float* wB = att + (m1 + gid + 8) * 72 + 2 * tig;
#pragma unroll
        for (int j = 0; j < 8; j++)
            *(float2*)(wB + 8 * j) = make_float2(e[2 * j] * inv, e[2 * j + 1] * inv);
    }
    __syncthreads();

    // ---- coalesced attn writeback ----
    for (int i = tid * 4; i < MT * KC; i += TPB * 4) {
        int r = i >> 6, c = i & 63;
        float4 v = *(float4*)(att + r * 72 + c);
        *(float4*)(attn_out + (row0 + r) * KC + c) = v;
    }

    // ---- GEMM3 (tf32 mma): comp[row][d] = attn @ clusters ----
    {
        float c3[8][4];
#pragma unroll
        for (int j = 0; j < 8; j++) { c3[j][0] = c3[j][1] = c3[j][2] = c3[j][3] = 0.f; }
        const float* Aa = att + (m1 + gid) * 72 + tig;     // rows m1+gid / +8, k = kc
        const float* Bp = csp + gid * 80 + tig * 20;
#pragma unroll
        for (int t = 0; t < 4; t++) {
            const int k0 = 16 * t;
            uint32_t a00 = f2t(Aa[k0]),      a01 = f2t(Aa[576 + k0]);
            uint32_t a02 = f2t(Aa[k0 + 4]),  a03 = f2t(Aa[576 + k0 + 4]);
            uint32_t a10 = f2t(Aa[k0 + 8]),  a11 = f2t(Aa[576 + k0 + 8]);
            uint32_t a12 = f2t(Aa[k0 + 12]), a13 = f2t(Aa[576 + k0 + 12]);
#pragma unroll
            for (int j = 0; j < 8; j++) {
                float4 b = *(const float4*)(Bp + j * 640 + 4 * t);
                mma8(c3[j], a00, a01, a02, a03, BITS(b.x), BITS(b.y));
                mma8(c3[j], a10, a11, a12, a13, BITS(b.z), BITS(b.w));
            }
        }
        float* outA = comp + (row0 + m1 + gid) * DIM + 2 * tig;
        float* outB = comp + (row0 + m1 + gid + 8) * DIM + 2 * tig;
#pragma unroll
        for (int j = 0; j < 8; j++) {
            *(float2*)(outA + 8 * j) = make_float2(c3[j][0], c3[j][1]);
            *(float2*)(outB + 8 * j) = make_float2(c3[j][2], c3[j][3]);
        }
    }
}

// ---------------- launch ----------------
extern "C" void kernel_launch(void* const* d_in, const int* in_sizes, int n_in,
                              void* d_out, int out_size) {
    const float* W  = (const float*)d_in[0];
    const float* C0 = (const float*)d_in[1];
    float* out  = (float*)d_out;
    float* comp = out;                                    // [N, D]
    float* clus = out + (size_t)NROWS * DIM;              // [K, D]
    float* attn = clus + (size_t)KC * DIM;                // [N, K]

    int sms = 0;
    cudaDeviceGetAttribute(&sms, cudaDevAttrMultiProcessorCount, 0);
    if (sms <= 0 || sms > MAXGRID) sms = MAXGRID;
    const int grid_iter = 2 * sms;                        // 2 CTAs/SM, bid%SMs pairing

    const int smem_iter  = 23744 * (int)sizeof(float);    // 94976 B  -> occ 2
    const int smem_final = 28864 * (int)sizeof(float);    // 115456 B -> occ 2
    cudaFuncSetAttribute(iter_fused, cudaFuncAttributeMaxDynamicSharedMemorySize, smem_iter);
    cudaFuncSetAttribute(final_fused, cudaFuncAttributeMaxDynamicSharedMemorySize, smem_final);

    init_kernel<<<NROWS / TPB, TPB>>>(W, C0);
    for (int it = 0; it < ITERS; it++)
        iter_fused<<<grid_iter, TPB, smem_iter>>>(it, W);
    final_fused<<<NROWS / MT, TPB, smem_final>>>(W, attn, comp, clus);
}

// round 17
// speedup vs baseline: 1.0780x; 1.0780x over previous
#include <cuda_runtime.h>
#include <math.h>
#include <stdint.h>

#define NROWS 131072
#define DIM 64
#define KC 64
#define ITERS 10
#define TPB 256
#define MT 128                    // rows per tile
#define NT (NROWS / MT)           // 1024 tiles
#define MAXGRID 148
#define NSLOTS (2 * MAXGRID)      // max partial slots (1 per block)
#define SLOTW 68                  // floats per (kc, slot) chunk; d==64 -> colsum

// ---------------- device globals (no cudaMalloc allowed) ----------------
__device__ float g_clusters[KC * DIM];
__device__ float g_prev[KC * DIM];          // clusters used by last active iteration
__device__ float g_part[(size_t)KC * NSLOTS * SLOTW];    // kc-major: [kc][slot][d]
__device__ float g_normk[KC];
__device__ float g_wsq[NROWS];
__device__ int   g_done;
__device__ volatile int g_sync[2];

// ---------------- helpers ----------------
__device__ __forceinline__ uint32_t f2t(float x) {
    uint32_t u;
    asm("cvt.rna.tf32.f32 %0, %1;" : "=r"(u) : "f"(x));
    return u;
}
__device__ __forceinline__ float fsqrt_fast(float x) {
    float r;
    asm("sqrt.approx.f32 %0, %1;" : "=f"(r) : "f"(x));
    return r;
}
__device__ __forceinline__ void mma8(float c[4], uint32_t a0, uint32_t a1, uint32_t a2,
                                     uint32_t a3, uint32_t b0, uint32_t b1) {
    asm("mma.sync.aligned.m16n8k8.row.col.f32.tf32.tf32.f32 "
        "{%0,%1,%2,%3},{%4,%5,%6,%7},{%8,%9},{%0,%1,%2,%3};"
        : "+f"(c[0]), "+f"(c[1]), "+f"(c[2]), "+f"(c[3])
        : "r"(a0), "r"(a1), "r"(a2), "r"(a3), "r"(b0), "r"(b1));
}
#define BITS(x) (__float_as_uint(x))
// permuted k layout: pos(k) = (k&3)*20 + (k>>2), row stride 80 -> float4 = 2 mma k-steps
#define CLP_POS(k) (((k) & 3) * 20 + ((k) >> 2))

// deterministic grid-wide sync: monotonic counters, per-launch target
__device__ __forceinline__ void gsync(int j, int target) {
    __syncthreads();
    if (threadIdx.x == 0) {
        __threadfence();
        atomicAdd((int*)&g_sync[j], 1);
        while (g_sync[j] < target) { }
        __threadfence();
    }
    __syncthreads();
}

// ---------------- init: flags, counters, cluster copy, ||w||^2 ----------------
__global__ void init_kernel(const float* __restrict__ W, const float* __restrict__ C0) {
    int gid = blockIdx.x * blockDim.x + threadIdx.x;   // NROWS threads
    if (gid == 0) { g_done = 0; g_sync[0] = 0; g_sync[1] = 0; }
    if (gid < KC * DIM) g_clusters[gid] = C0[gid];
    const float4* p = (const float4*)(W + (size_t)gid * DIM);
    float s = 0.f;
#pragma unroll
    for (int j = 0; j < 16; j++) {
        float4 v = p[j];
        s += v.x * v.x + v.y * v.y + v.z * v.z + v.w * v.w;
    }
    g_wsq[gid] = s;
}

// ---------------- fully fused iteration kernel (296 blocks, occ 2) ----------------
__global__ __launch_bounds__(TPB, 2) void iter_fused(int it, const float* __restrict__ W) {
    if (g_done) return;
    extern __shared__ float sm[];
    float* clp  = sm;          // [64][80] clusters, k-permuted tf32
    float* csq  = sm + 5120;   // [64] exact ||c||^2
    float* w    = sm + 5184;   // [128][72] W tile (tf32); col64=1, cols65-71=0
    float* att  = sm + 14400;  // [128][72] attn tile (tf32); reused as c2 stage at end
    float* wsqs = sm + 23616;  // [128]

    const int tid = threadIdx.x;
    const int lane = tid & 31, wid = tid >> 5;
    const int gid = lane >> 2, tig = lane & 3;
    const int m1 = wid * 16;            // GEMM1 row offset
    const int m2 = (wid & 3) * 16;      // GEMM2 kc offset
    const int rh = (wid >> 2) * 64;     // GEMM2 row-half offset
    const int target = (it + 1) * (int)gridDim.x;

    for (int i = tid; i < KC * DIM; i += TPB) {
        int n = i >> 6, k = i & 63;
        clp[n * 80 + CLP_POS(k)] = __uint_as_float(f2t(g_clusters[i]));
    }
    if (tid < KC) {
        float s = 0.f;
#pragma unroll
        for (int d = 0; d < DIM; d++) { float v = g_clusters[tid * DIM + d]; s += v * v; }
        csq[tid] = s;
    }
    // persistent ones/zeros in cols 64..71 of w (colsum trick)
    for (int i = tid; i < MT * 8; i += TPB) {
        int r = i >> 3, c = i & 7;
        w[r * 72 + 64 + c] = (c == 0) ? 1.0f : 0.0f;
    }

    float c2[9][4];
#pragma unroll
    for (int j = 0; j < 9; j++) { c2[j][0] = c2[j][1] = c2[j][2] = c2[j][3] = 0.f; }

    // ---- prefetch first tile into registers ----
    float4 rw[8];
    float wsq_pf = 0.f;
    {
        const float* src = W + (size_t)blockIdx.x * MT * DIM;
#pragma unroll
        for (int j = 0; j < 8; j++) rw[j] = *(const float4*)(src + tid * 4 + j * 1024);
        if (tid < MT) wsq_pf = g_wsq[(size_t)blockIdx.x * MT + tid];
    }

    for (int tile = blockIdx.x; tile < NT; tile += gridDim.x) {
        __syncthreads();   // w/att free (previous GEMM2 done; init done on first pass)
#pragma unroll
        for (int j = 0; j < 8; j++) {
            const int i = tid * 4 + j * 1024;
            float4 v = rw[j];
            v.x = __uint_as_float(f2t(v.x));
            v.y = __uint_as_float(f2t(v.y));
            v.z = __uint_as_float(f2t(v.z));
            v.w = __uint_as_float(f2t(v.w));
            *(float4*)(w + (i >> 6) * 72 + (i & 63)) = v;
        }
        if (tid < MT) wsqs[tid] = wsq_pf;
        __syncthreads();

        // issue prefetch for next tile (retires under GEMM1+softmax)
        const int nt = tile + (int)gridDim.x;
        if (nt < NT) {
            const float* src = W + (size_t)nt * MT * DIM;
#pragma unroll
            for (int j = 0; j < 8; j++) rw[j] = *(const float4*)(src + tid * 4 + j * 1024);
            if (tid < MT) wsq_pf = g_wsq[(size_t)nt * MT + tid];
        }

        // ---- GEMM1: C1[row][kc] = W * C^T  (B via vectorized permuted loads) ----
        float c1[8][4];
#pragma unroll
        for (int j = 0; j < 8; j++) { c1[j][0] = c1[j][1] = c1[j][2] = c1[j][3] = 0.f; }
        const float* Ab = w + (m1 + gid) * 72 + tig;
        const float* Bp = clp + gid * 80 + tig * 20;
#pragma unroll
        for (int t = 0; t < 4; t++) {
            const int k0 = 16 * t;
            uint32_t a00 = BITS(Ab[k0]),     a01 = BITS(Ab[576 + k0]);
            uint32_t a02 = BITS(Ab[k0 + 4]), a03 = BITS(Ab[576 + k0 + 4]);
            uint32_t a10 = BITS(Ab[k0 + 8]),  a11 = BITS(Ab[576 + k0 + 8]);
            uint32_t a12 = BITS(Ab[k0 + 12]), a13 = BITS(Ab[576 + k0 + 12]);
#pragma unroll
            for (int j = 0; j < 8; j++) {
                float4 b = *(const float4*)(Bp + j * 640 + 4 * t);
                mma8(c1[j], a00, a01, a02, a03, BITS(b.x), BITS(b.y));
                mma8(c1[j], a10, a11, a12, a13, BITS(b.z), BITS(b.w));
            }
        }

        // ---- softmax row A (m1+gid), then row B (m1+gid+8) ----
        {
            float ws = wsqs[m1 + gid];
            float e[16], mn = 3.4e38f;
#pragma unroll
            for (int j = 0; j < 8; j++) {
                float c0 = csq[8 * j + 2 * tig], c1v = csq[8 * j + 2 * tig + 1];
                float d0 = fsqrt_fast(fmaxf(ws + c0 - 2.f * c1[j][0], 0.f));
                float d1 = fsqrt_fast(fmaxf(ws + c1v - 2.f * c1[j][1], 0.f));
                e[2 * j] = d0; e[2 * j + 1] = d1;
                mn = fminf(mn, fminf(d0, d1));
            }
            mn = fminf(mn, __shfl_xor_sync(0xffffffffu, mn, 1));
            mn = fminf(mn, __shfl_xor_sync(0xffffffffu, mn, 2));
            float s = 0.f;
#pragma unroll
            for (int j = 0; j < 16; j++) { e[j] = __expf(mn - e[j]); s += e[j]; }
            s += __shfl_xor_sync(0xffffffffu, s, 1);
            s += __shfl_xor_sync(0xffffffffu, s, 2);
            float inv = 1.f / s;
            float* wA = att + (m1 + gid) * 72 + 2 * tig;
#pragma unroll
            for (int j = 0; j < 8; j++) {
                float2 v = make_float2(__uint_as_float(f2t(e[2 * j] * inv)),
                                       __uint_as_float(f2t(e[2 * j + 1] * inv)));
                *(float2*)(wA + 8 * j) = v;
            }
        }
        {
            float ws = wsqs[m1 + gid + 8];
            float e[16], mn = 3.4e38f;
#pragma unroll
            for (int j = 0; j < 8; j++) {
                float c0 = csq[8 * j + 2 * tig], c1v = csq[8 * j + 2 * tig + 1];
                float d0 = fsqrt_fast(fmaxf(ws + c0 - 2.f * c1[j][2], 0.f));
                float d1 = fsqrt_fast(fmaxf(ws + c1v - 2.f * c1[j][3], 0.f));
                e[2 * j] = d0; e[2 * j + 1] = d1;
                mn = fminf(mn, fminf(d0, d1));
            }
            mn = fminf(mn, __shfl_xor_sync(0xffffffffu, mn, 1));
            mn = fminf(mn, __shfl_xor_sync(0xffffffffu, mn, 2));
            float s = 0.f;
#pragma unroll
            for (int j = 0; j < 16; j++) { e[j] = __expf(mn - e[j]); s += e[j]; }
            s += __shfl_xor_sync(0xffffffffu, s, 1);
            s += __shfl_xor_sync(0xffffffffu, s, 2);
            float inv = 1.f / s;
            float* wB = att + (m1 + gid + 8) * 72 + 2 * tig;
#pragma unroll
            for (int j = 0; j < 8; j++) {
                float2 v = make_float2(__uint_as_float(f2t(e[2 * j] * inv)),
                                       __uint_as_float(f2t(e[2 * j + 1] * inv)));
                *(float2*)(wB + 8 * j) = v;
            }
        }
        __syncthreads();

        // ---- GEMM2: C2[kc][d] += attn^T * W  (9th n-frag vs ones col = colsum) ----
        const float* A2 = att + (rh + tig) * 72 + m2 + gid;
        const float* B2 = w + (rh + tig) * 72 + gid;
#pragma unroll 4
        for (int s = 0; s < 8; s++) {
            const int o = s * 8 * 72;
            uint32_t a0 = BITS(A2[o]);
            uint32_t a1 = BITS(A2[o + 8]);
            uint32_t a2 = BITS(A2[o + 4 * 72]);
            uint32_t a3 = BITS(A2[o + 4 * 72 + 8]);
#pragma unroll
            for (int j = 0; j < 9; j++) {
                uint32_t b0 = BITS(B2[o + 8 * j]);
                uint32_t b1 = BITS(B2[o + 4 * 72 + 8 * j]);
                mma8(c2[j], a0, a1, a2, a3, b0, b1);
            }
        }
    }

    // ---- combine row-halves in smem, write ONE partial slot per block (kc-major gmem) ----
    __syncthreads();
    {
        float* stage = att;             // [64][72] c2 of row-half 1
        if (rh) {
#pragma unroll
            for (int j = 0; j < 8; j++) {
                *(float2*)(stage + (m2 + gid) * 72 + 8 * j + 2 * tig) = make_float2(c2[j][0], c2[j][1]);
                *(float2*)(stage + (m2 + gid + 8) * 72 + 8 * j + 2 * tig) = make_float2(c2[j][2], c2[j][3]);
            }
            if (tig == 0) {
                stage[(m2 + gid) * 72 + 64] = c2[8][0];
                stage[(m2 + gid + 8) * 72 + 64] = c2[8][2];
            }
        }
        __syncthreads();
        if (!rh) {
            // row kc lives at g_part[kc*NSLOTS*SLOTW + blockIdx.x*SLOTW + d]
            float* P0 = g_part + (size_t)blockIdx.x * SLOTW;
#pragma unroll
            for (int j = 0; j < 8; j++) {
                float2 s0 = *(float2*)(stage + (m2 + gid) * 72 + 8 * j + 2 * tig);
                float2 s1 = *(float2*)(stage + (m2 + gid + 8) * 72 + 8 * j + 2 * tig);
                *(float2*)(P0 + (size_t)(m2 + gid) * NSLOTS * SLOTW + 8 * j + 2 * tig) =
                    make_float2(c2[j][0] + s0.x, c2[j][1] + s0.y);
                *(float2*)(P0 + (size_t)(m2 + gid + 8) * NSLOTS * SLOTW + 8 * j + 2 * tig) =
                    make_float2(c2[j][2] + s1.x, c2[j][3] + s1.y);
            }
            if (tig == 0) {
                P0[(size_t)(m2 + gid) * NSLOTS * SLOTW + 64] = c2[8][0] + stage[(m2 + gid) * 72 + 64];
                P0[(size_t)(m2 + gid + 8) * NSLOTS * SLOTW + 64] = c2[8][2] + stage[(m2 + gid + 8) * 72 + 64];
            }
        }
    }

    gsync(0, target);

    // ---- blocks 0..63 reduce partials for their k (coalesced contiguous scan) ----
    float nv = 0.f, ov = 0.f;
    const int kblk = blockIdx.x;
    if (kblk < 64) {
        float* r_num = sm;          // [4][64]
        float* r_den = sm + 256;    // [4]
        float* s_nrm = sm + 264;    // [2]
        const int q = tid >> 6, d = tid & 63;
        const int nslots = (int)gridDim.x;
        float s = 0.f, sden = 0.f;
        const float* base = g_part + (size_t)kblk * NSLOTS * SLOTW;
        for (int b = q; b < nslots; b += 4) {
            const float* P = base + (size_t)b * SLOTW;
            s += P[d];
            if (d == 0) sden += P[64];
        }
        r_num[q * 64 + d] = s;
        if (d == 0) r_den[q] = sden;
        __syncthreads();
        if (tid < 64) {
            float num = (r_num[tid] + r_num[64 + tid]) + (r_num[128 + tid] + r_num[192 + tid]);
            float den = (r_den[0] + r_den[1]) + (r_den[2] + r_den[3]);
            nv = num / den;
            ov = g_clusters[kblk * 64 + tid];
            float x = (nv - ov) * (nv - ov);
#pragma unroll
            for (int o = 16; o > 0; o >>= 1) x += __shfl_xor_sync(0xffffffffu, x, o);
            if ((tid & 31) == 0) s_nrm[tid >> 5] = x;
        }
        __syncthreads();
        if (tid == 0) g_normk[kblk] = s_nrm[0] + s_nrm[1];
    }

    gsync(1, target);

    // ---- convergence decision (redundant per block) + commit ----
    if (kblk < 64) {
        __shared__ int s_conv;
        if (tid == 0) {
            float t = 0.f;
            for (int k = 0; k < 64; k++) t += g_normk[k];
            int conv = (sqrtf(t) <= 1e-4f) ? 1 : 0;
            s_conv = conv;
            if (kblk == 0 && conv) g_done = 1;   // freeze for remaining launches
        }
        __syncthreads();
        if (tid < 64) {
            g_prev[kblk * 64 + tid] = ov;
            g_clusters[kblk * 64 + tid] = s_conv ? ov : nv;
        }
    }
}

// ---------------- fused final: attn (tf32 GEMM1 + fp32 softmax) + compressed (tf32 GEMM3) ----------------
__global__ __launch_bounds__(TPB, 2) void final_fused(const float* __restrict__ W,
                                                      float* __restrict__ attn_out,
                                                      float* __restrict__ comp,
                                                      float* __restrict__ clus_out) {
    extern __shared__ float sm[];
    float* clp = sm;          // [64][80] tf32(g_prev), k-permuted (B of GEMM1)
    float* csq = sm + 5120;   // [64] exact ||c_prev||^2
    float* w   = sm + 5184;   // [128][72] tf32 W tile
    float* att = sm + 14400;  // [128][72] fp32 attn
    float* csp = sm + 23616;  // [64][80] tf32(g_clusters), d-major k-permuted (B of GEMM3)
    float* wsq = sm + 28736;  // [128]

    const int tid = threadIdx.x;
    const int lane = tid & 31, wid = tid >> 5;
    const int gid = lane >> 2, tig = lane & 3;
    const int m1 = wid * 16;
    const size_t row0 = (size_t)blockIdx.x * MT;

    for (int i = tid; i < KC * DIM; i += TPB) {
        int kc = i >> 6, d = i & 63;
        clp[kc * 80 + CLP_POS(d)] = __uint_as_float(f2t(g_prev[i]));      // B1[n=kc][k=d]
        float cv = g_clusters[i];
        csp[d * 80 + CLP_POS(kc)] = __uint_as_float(f2t(cv));             // B3[n=d][k=kc]
        if (blockIdx.x == 0) clus_out[i] = cv;
    }
    if (tid < KC) {
        float s = 0.f;
#pragma unroll
        for (int d = 0; d < DIM; d++) { float v = g_prev[tid * DIM + d]; s += v * v; }
        csq[tid] = s;
    }
    for (int i = tid * 4; i < MT * DIM; i += TPB * 4) {
        float4 v = *(const float4*)(W + row0 * DIM + i);
        v.x = __uint_as_float(f2t(v.x));
        v.y = __uint_as_float(f2t(v.y));
        v.z = __uint_as_float(f2t(v.z));
        v.w = __uint_as_float(f2t(v.w));
        *(float4*)(w + (i >> 6) * 72 + (i & 63)) = v;
    }
    if (tid < MT) wsq[tid] = g_wsq[row0 + tid];
    __syncthreads();

    // ---- GEMM1 (tf32 mma, vectorized B): C1[row][kc] = W * C_prev^T ----
    float c1[8][4];
#pragma unroll
    for (int j = 0; j < 8; j++) { c1[j][0] = c1[j][1] = c1[j][2] = c1[j][3] = 0.f; }
    {
        const float* Ab = w + (m1 + gid) * 72 + tig;
        const float* Bp = clp + gid * 80 + tig * 20;
#pragma unroll
        for (int t = 0; t < 4; t++) {
            const int k0 = 16 * t;
            uint32_t a00 = BITS(Ab[k0]),     a01 = BITS(Ab[576 + k0]);
            uint32_t a02 = BITS(Ab[k0 + 4]), a03 = BITS(Ab[576 + k0 + 4]);
            uint32_t a10 = BITS(Ab[k0 + 8]),  a11 = BITS(Ab[576 + k0 + 8]);
            uint32_t a12 = BITS(Ab[k0 + 12]), a13 = BITS(Ab[576 + k0 + 12]);
#pragma unroll
            for (int j = 0; j < 8; j++) {
                float4 b = *(const float4*)(Bp + j * 640 + 4 * t);
                mma8(c1[j], a00, a01, a02, a03, BITS(b.x), BITS(b.y));
                mma8(c1[j], a10, a11, a12, a13, BITS(b.z), BITS(b.w));
            }
        }
    }

    // ---- softmax rows (fp32 attn into smem) ----
    {
        float ws = wsq[m1 + gid];
        float e[16], mn = 3.4e38f;
#pragma unroll
        for (int j = 0; j < 8; j++) {
            float c0 = csq[8 * j + 2 * tig], c1v = csq[8 * j + 2 * tig + 1];
            float d0 = fsqrt_fast(fmaxf(ws + c0 - 2.f * c1[j][0], 0.f));
            float d1 = fsqrt_fast(fmaxf(ws + c1v - 2.f * c1[j][1], 0.f));
            e[2 * j] = d0; e[2 * j + 1] = d1;
            mn = fminf(mn, fminf(d0, d1));
        }
        mn = fminf(mn, __shfl_xor_sync(0xffffffffu, mn, 1));
        mn = fminf(mn, __shfl_xor_sync(0xffffffffu, mn, 2));
        float s = 0.f;
#pragma unroll
        for (int j = 0; j < 16; j++) { e[j] = __expf(mn - e[j]); s += e[j]; }
        s += __shfl_xor_sync(0xffffffffu, s, 1);
        s += __shfl_xor_sync(0xffffffffu, s, 2);
        float inv = 1.f / s;
        float* wA = att + (m1 + gid) * 72 + 2 * tig;
#pragma unroll
        for (int j = 0; j < 8; j++)
            *(float2*)(wA + 8 * j) = make_float2(e[2 * j] * inv, e[2 * j + 1] * inv);
    }
    {
        float ws = wsq[m1 + gid + 8];
        float e[16], mn = 3.4e38f;
#pragma unroll
        for (int j = 0; j < 8; j++) {
            float c0 = csq[8 * j + 2 * tig], c1v = csq[8 * j + 2 * tig + 1];
            float d0 = fsqrt_fast(fmaxf(ws + c0 - 2.f * c1[j][2], 0.f));
            float d1 = fsqrt_fast(fmaxf(ws + c1v - 2.f * c1[j][3], 0.f));
            e[2 * j] = d0; e[2 * j + 1] = d1;
            mn = fminf(mn, fminf(d0, d1));
        }
        mn = fminf(mn, __shfl_xor_sync(0xffffffffu, mn, 1));
        mn = fminf(mn, __shfl_xor_sync(0xffffffffu, mn, 2));
        float s = 0.f;
#pragma unroll
        for (int j = 0; j < 16; j++) { e[j] = __expf(mn - e[j]); s += e[j]; }
        s += __shfl_xor_sync(0xffffffffu, s, 1);
        s += __shfl_xor_sync(0xffffffffu, s, 2);
        float inv = 1.f / s;
        float* wB = att + (m1 + gid + 8) * 72 + 2 * tig;
#pragma unroll
        for (int j = 0; j < 8; j++)
            *(float2*)(wB + 8 * j) = make_float2(e[2 * j] * inv, e[2 * j + 1] * inv);
    }
    __syncthreads();

    // ---- coalesced attn writeback ----
    for (int i = tid * 4; i < MT * KC; i += TPB * 4) {
        int r = i >> 6, c = i & 63;
        float4 v = *(float4*)(att + r * 72 + c);
        *(float4*)(attn_out + (row0 + r) * KC + c) = v;
    }

    // ---- GEMM3 (tf32 mma): comp[row][d] = attn @ clusters ----
    {
        float c3[8][4];
#pragma unroll
        for (int j = 0; j < 8; j++) { c3[j][0] = c3[j][1] = c3[j][2] = c3[j][3] = 0.f; }
        const float* Aa = att + (m1 + gid) * 72 + tig;     // rows m1+gid / +8, k = kc
        const float* Bp = csp + gid * 80 + tig * 20;
#pragma unroll
        for (int t = 0; t < 4; t++) {
            const int k0 = 16 * t;
            uint32_t a00 = f2t(Aa[k0]),      a01 = f2t(Aa[576 + k0]);
            uint32_t a02 = f2t(Aa[k0 + 4]),  a03 = f2t(Aa[576 + k0 + 4]);
            uint32_t a10 = f2t(Aa[k0 + 8]),  a11 = f2t(Aa[576 + k0 + 8]);
            uint32_t a12 = f2t(Aa[k0 + 12]), a13 = f2t(Aa[576 + k0 + 12]);
#pragma unroll
            for (int j = 0; j < 8; j++) {
                float4 b = *(const float4*)(Bp + j * 640 + 4 * t);
                mma8(c3[j], a00, a01, a02, a03, BITS(b.x), BITS(b.y));
                mma8(c3[j], a10, a11, a12, a13, BITS(b.z), BITS(b.w));
            }
        }
        float* outA = comp + (row0 + m1 + gid) * DIM + 2 * tig;
        float* outB = comp + (row0 + m1 + gid + 8) * DIM + 2 * tig;
#pragma unroll
        for (int j = 0; j < 8; j++) {
            *(float2*)(outA + 8 * j) = make_float2(c3[j][0], c3[j][1]);
            *(float2*)(outB + 8 * j) = make_float2(c3[j][2], c3[j][3]);
        }
    }
}

// ---------------- launch ----------------
extern "C" void kernel_launch(void* const* d_in, const int* in_sizes, int n_in,
                              void* d_out, int out_size) {
    const float* W  = (const float*)d_in[0];
    const float* C0 = (const float*)d_in[1];
    float* out  = (float*)d_out;
    float* comp = out;                                    // [N, D]
    float* clus = out + (size_t)NROWS * DIM;              // [K, D]
    float* attn = clus + (size_t)KC * DIM;                // [N, K]

    int sms = 0;
    cudaDeviceGetAttribute(&sms, cudaDevAttrMultiProcessorCount, 0);
    if (sms <= 0 || sms > MAXGRID) sms = MAXGRID;
    const int grid_iter = 2 * sms;                        // 2 CTAs/SM, bid%SMs pairing

    const int smem_iter  = 23744 * (int)sizeof(float);    // 94976 B  -> occ 2
    const int smem_final = 28864 * (int)sizeof(float);    // 115456 B -> occ 2
    cudaFuncSetAttribute(iter_fused, cudaFuncAttributeMaxDynamicSharedMemorySize, smem_iter);
    cudaFuncSetAttribute(final_fused, cudaFuncAttributeMaxDynamicSharedMemorySize, smem_final);

    init_kernel<<<NROWS / TPB, TPB>>>(W, C0);
    for (int it = 0; it < ITERS; it++)
        iter_fused<<<grid_iter, TPB, smem_iter>>>(it, W);
    final_fused<<<NROWS / MT, TPB, smem_final>>>(W, attn, comp, clus);
}